// round 1
// baseline (speedup 1.0000x reference)
#include <cuda_runtime.h>

#define B_  4
#define S_  2048
#define D_  1024
#define H_  16
#define DH_ 64
#define M_  (B_*S_)   // 8192

// Scratch (static __device__ — no allocation)
__device__ float g_Q[(size_t)B_*H_*S_*DH_];   // [B,H,S,DH]
__device__ float g_K[(size_t)B_*H_*S_*DH_];
__device__ float g_V[(size_t)B_*H_*S_*DH_];
__device__ float g_AO[(size_t)M_*D_];         // [B*S, D] merged heads

// ---------------------------------------------------------------------------
// SGEMM NT:  C[m,n] = sum_k A[m,k]*W[n,k] + bias[n]
// A: [M_,1024] row-major, W: [1024,1024] row-major. 128x128x16 tiles,
// 256 threads, 8x8 accumulators per thread.
// mode 0/1/2: A = Aext (x), scatter into g_Q/g_K/g_V as [B,H,S,DH]
// mode 3:     A = g_AO, plain row-major store to Oext
// ---------------------------------------------------------------------------
#define BM 128
#define BN 128
#define BK 16
#define AST 132   // padded smem stride (k-major: As[k*AST + m])

__global__ __launch_bounds__(256) void sgemm_nt(const float* __restrict__ Aext,
                                                const float* __restrict__ W,
                                                const float* __restrict__ bias,
                                                float* __restrict__ Oext,
                                                int mode) {
    __shared__ float As[BK * AST];
    __shared__ float Bs[BK * AST];

    const float* A = (mode == 3) ? g_AO : Aext;
    float* qkv = (mode == 0) ? g_Q : (mode == 1) ? g_K : g_V;

    const int tid   = threadIdx.x;
    const int mBase = blockIdx.y * BM;
    const int nBase = blockIdx.x * BN;
    const int tx = tid & 15;        // 0..15 -> n micro-tile
    const int ty = tid >> 4;        // 0..15 -> m micro-tile

    const int lrow = tid >> 2;          // 0..63
    const int lkq  = (tid & 3) << 2;    // 0,4,8,12

    float acc[8][8];
    #pragma unroll
    for (int i = 0; i < 8; i++)
        #pragma unroll
        for (int j = 0; j < 8; j++) acc[i][j] = 0.f;

    for (int kb = 0; kb < 1024; kb += BK) {
        // load A tile (128 rows x 16 k) transposed into As[k][m]
        #pragma unroll
        for (int half = 0; half < 2; half++) {
            int row = lrow + half * 64;
            float4 av = *(const float4*)&A[(size_t)(mBase + row) * 1024 + kb + lkq];
            As[(lkq + 0) * AST + row] = av.x;
            As[(lkq + 1) * AST + row] = av.y;
            As[(lkq + 2) * AST + row] = av.z;
            As[(lkq + 3) * AST + row] = av.w;
            float4 bv = *(const float4*)&W[(size_t)(nBase + row) * 1024 + kb + lkq];
            Bs[(lkq + 0) * AST + row] = bv.x;
            Bs[(lkq + 1) * AST + row] = bv.y;
            Bs[(lkq + 2) * AST + row] = bv.z;
            Bs[(lkq + 3) * AST + row] = bv.w;
        }
        __syncthreads();

        #pragma unroll
        for (int k = 0; k < BK; k++) {
            float a[8], b[8];
            *(float4*)&a[0] = *(const float4*)&As[k * AST + ty * 8];
            *(float4*)&a[4] = *(const float4*)&As[k * AST + ty * 8 + 4];
            *(float4*)&b[0] = *(const float4*)&Bs[k * AST + tx * 8];
            *(float4*)&b[4] = *(const float4*)&Bs[k * AST + tx * 8 + 4];
            #pragma unroll
            for (int i = 0; i < 8; i++)
                #pragma unroll
                for (int j = 0; j < 8; j++)
                    acc[i][j] += a[i] * b[j];
        }
        __syncthreads();
    }

    // epilogue
    if (mode == 3) {
        #pragma unroll
        for (int i = 0; i < 8; i++) {
            int m = mBase + ty * 8 + i;
            #pragma unroll
            for (int j = 0; j < 8; j++) {
                int n = nBase + tx * 8 + j;
                Oext[(size_t)m * 1024 + n] = acc[i][j] + bias[n];
            }
        }
    } else {
        #pragma unroll
        for (int i = 0; i < 8; i++) {
            int m = mBase + ty * 8 + i;
            int b  = m >> 11;        // /S_
            int s  = m & 2047;
            #pragma unroll
            for (int j = 0; j < 8; j++) {
                int n  = nBase + tx * 8 + j;
                int h  = n >> 6;
                int dh = n & 63;
                qkv[(((size_t)(b * H_ + h)) * S_ + s) * DH_ + dh] = acc[i][j] + bias[n];
            }
        }
    }
}

// ---------------------------------------------------------------------------
// Flash attention (causal), fp32. One thread per query row, 128 rows/block.
// K/V tiles of 64 keys in smem; 16-key register chunks, two-pass softmax.
// ---------------------------------------------------------------------------
#define BQ 128
#define KT 64

__global__ __launch_bounds__(128) void flash_attn() {
    __shared__ float Ks[KT * DH_];
    __shared__ float Vs[KT * DH_];

    const int bh = blockIdx.y;            // b*H + h
    const int q0 = blockIdx.x * BQ;
    const int t  = threadIdx.x;
    const int qi = q0 + t;

    const float* Qb = g_Q + (size_t)bh * S_ * DH_;
    const float* Kb = g_K + (size_t)bh * S_ * DH_;
    const float* Vb = g_V + (size_t)bh * S_ * DH_;

    float q[DH_];
    #pragma unroll
    for (int i = 0; i < DH_ / 4; i++) {
        float4 v = *(const float4*)&Qb[(size_t)qi * DH_ + i * 4];
        q[i*4+0] = v.x; q[i*4+1] = v.y; q[i*4+2] = v.z; q[i*4+3] = v.w;
    }

    float o[DH_];
    #pragma unroll
    for (int d = 0; d < DH_; d++) o[d] = 0.f;
    float m = -1e30f, l = 0.f;
    const float scale = 0.125f;  // 1/sqrt(64)

    const int kend = q0 + BQ;    // causal: only keys < kend matter for this block
    for (int kt = 0; kt < kend; kt += KT) {
        __syncthreads();
        // cooperative tile load: 64x64 floats = 1024 float4, 8 per thread
        const float4* Kg = (const float4*)&Kb[(size_t)kt * DH_];
        const float4* Vg = (const float4*)&Vb[(size_t)kt * DH_];
        float4* Ks4 = (float4*)Ks;
        float4* Vs4 = (float4*)Vs;
        #pragma unroll
        for (int r = 0; r < 8; r++) {
            Ks4[r * 128 + t] = Kg[r * 128 + t];
            Vs4[r * 128 + t] = Vg[r * 128 + t];
        }
        __syncthreads();

        #pragma unroll 1
        for (int j0 = 0; j0 < KT; j0 += 16) {
            float sreg[16];
            float tmax = -1e30f;
            #pragma unroll
            for (int jj = 0; jj < 16; jj++) {
                const int kidx = kt + j0 + jj;
                const float4* k4 = (const float4*)&Ks[(j0 + jj) * DH_];
                float s0 = 0.f, s1 = 0.f, s2 = 0.f, s3 = 0.f;
                #pragma unroll
                for (int d4 = 0; d4 < DH_ / 4; d4++) {
                    float4 kv = k4[d4];
                    s0 += q[d4*4+0] * kv.x;
                    s1 += q[d4*4+1] * kv.y;
                    s2 += q[d4*4+2] * kv.z;
                    s3 += q[d4*4+3] * kv.w;
                }
                float s = ((s0 + s1) + (s2 + s3)) * scale;
                s = (kidx <= qi) ? s : -1e30f;
                sreg[jj] = s;
                tmax = fmaxf(tmax, s);
            }
            float mnew = fmaxf(m, tmax);
            if (mnew > m) {
                float corr = __expf(m - mnew);
                l *= corr;
                #pragma unroll
                for (int d = 0; d < DH_; d++) o[d] *= corr;
                m = mnew;
            }
            #pragma unroll
            for (int jj = 0; jj < 16; jj++) {
                float p = __expf(sreg[jj] - m);
                l += p;
                const float4* v4 = (const float4*)&Vs[(j0 + jj) * DH_];
                #pragma unroll
                for (int d4 = 0; d4 < DH_ / 4; d4++) {
                    float4 vv = v4[d4];
                    o[d4*4+0] += p * vv.x;
                    o[d4*4+1] += p * vv.y;
                    o[d4*4+2] += p * vv.z;
                    o[d4*4+3] += p * vv.w;
                }
            }
        }
    }

    // write merged-head output row: AO[b*S+qi, h*64 .. h*64+63]
    const float inv = 1.0f / l;
    const int b = bh >> 4;
    const int h = bh & 15;
    float* dst = &g_AO[((size_t)(b * S_ + qi)) * D_ + h * DH_];
    #pragma unroll
    for (int d4 = 0; d4 < DH_ / 4; d4++) {
        float4 vv;
        vv.x = o[d4*4+0] * inv;
        vv.y = o[d4*4+1] * inv;
        vv.z = o[d4*4+2] * inv;
        vv.w = o[d4*4+3] * inv;
        *(float4*)&dst[d4 * 4] = vv;
    }
}

// ---------------------------------------------------------------------------
extern "C" void kernel_launch(void* const* d_in, const int* in_sizes, int n_in,
                              void* d_out, int out_size) {
    const float* x  = (const float*)d_in[0];
    const float* Wq = (const float*)d_in[1];
    const float* bq = (const float*)d_in[2];
    const float* Wk = (const float*)d_in[3];
    const float* bk = (const float*)d_in[4];
    const float* Wv = (const float*)d_in[5];
    const float* bv = (const float*)d_in[6];
    const float* Wo = (const float*)d_in[7];
    const float* bo = (const float*)d_in[8];
    float* out = (float*)d_out;

    dim3 gg(D_ / BN, M_ / BM);   // (8, 64)
    sgemm_nt<<<gg, 256>>>(x, Wq, bq, nullptr, 0);
    sgemm_nt<<<gg, 256>>>(x, Wk, bk, nullptr, 1);
    sgemm_nt<<<gg, 256>>>(x, Wv, bv, nullptr, 2);

    dim3 fg(S_ / BQ, B_ * H_);   // (16, 64)
    flash_attn<<<fg, 128>>>();

    sgemm_nt<<<gg, 256>>>(nullptr, Wo, bo, out, 3);
}

// round 2
// speedup vs baseline: 1.5997x; 1.5997x over previous
#include <cuda_runtime.h>
#include <cuda_bf16.h>
#include <cstdint>

#define B_  4
#define S_  2048
#define D_  1024
#define H_  16
#define DH_ 64
#define M_  (B_*S_)   // 8192

// ---------------- scratch (static __device__, no allocation) ----------------
__device__ float g_Q[(size_t)B_*H_*S_*DH_];   // [B,H,S,DH]
__device__ float g_K[(size_t)B_*H_*S_*DH_];
__device__ float g_V[(size_t)B_*H_*S_*DH_];
__device__ float g_AO[(size_t)M_*D_];         // [B*S, D] merged heads

__device__ __nv_bfloat16 g_xhi[(size_t)M_*D_];
__device__ __nv_bfloat16 g_xlo[(size_t)M_*D_];
__device__ __nv_bfloat16 g_AOhi[(size_t)M_*D_];
__device__ __nv_bfloat16 g_AOlo[(size_t)M_*D_];
__device__ __nv_bfloat16 g_Whi[4][(size_t)D_*D_];
__device__ __nv_bfloat16 g_Wlo[4][(size_t)D_*D_];

// ---------------------------------------------------------------------------
// split-precision conversion: fp32 -> (bf16 hi, bf16 lo)
// ---------------------------------------------------------------------------
__global__ __launch_bounds__(256) void cvt_split(const float4* __restrict__ src,
                                                 __nv_bfloat162* __restrict__ hi,
                                                 __nv_bfloat162* __restrict__ lo,
                                                 int n4) {
    int i = blockIdx.x * blockDim.x + threadIdx.x;
    if (i >= n4) return;
    float4 v = src[i];
    __nv_bfloat16 hx = __float2bfloat16_rn(v.x);
    __nv_bfloat16 hy = __float2bfloat16_rn(v.y);
    __nv_bfloat16 hz = __float2bfloat16_rn(v.z);
    __nv_bfloat16 hw = __float2bfloat16_rn(v.w);
    __nv_bfloat16 lx = __float2bfloat16_rn(v.x - __bfloat162float(hx));
    __nv_bfloat16 ly = __float2bfloat16_rn(v.y - __bfloat162float(hy));
    __nv_bfloat16 lz = __float2bfloat16_rn(v.z - __bfloat162float(hz));
    __nv_bfloat16 lw = __float2bfloat16_rn(v.w - __bfloat162float(hw));
    hi[2*i]   = __nv_bfloat162(hx, hy);
    hi[2*i+1] = __nv_bfloat162(hz, hw);
    lo[2*i]   = __nv_bfloat162(lx, ly);
    lo[2*i+1] = __nv_bfloat162(lz, lw);
}

// ---------------------------------------------------------------------------
// bf16x3 split GEMM:  C[m,n] = sum_k A[m,k]*W[n,k] + bias[n]
// A hi/lo: [M,1024] bf16, W hi/lo: [1024,1024] bf16.
// 128x128x32 tiles, 256 threads (8 warps = 2m x 4n), warp tile 64x32.
// mma.sync.m16n8k16 bf16, fp32 accum:  Ahi*Bhi + Ahi*Blo + Alo*Bhi.
// cp.async double-buffered smem, 80B row pitch -> conflict-free ldmatrix.
// ---------------------------------------------------------------------------
#define BM 128
#define BN 128
#define BK 32
#define LDT 40                 // bf16 per smem row (80 bytes, 5 chunks of 16B)
#define TILE_BYTES (BM*LDT*2)  // 10240
#define STAGE_BYTES (4*TILE_BYTES) // 40960 (Ahi, Alo, Bhi, Blo)

#define CP16(dst, src) \
    asm volatile("cp.async.cg.shared.global [%0], [%1], 16;\n" :: "r"(dst), "l"(src))

#define LDM_X4(r0,r1,r2,r3, addr) \
    asm volatile("ldmatrix.sync.aligned.m8n8.x4.shared.b16 {%0,%1,%2,%3}, [%4];" \
                 : "=r"(r0),"=r"(r1),"=r"(r2),"=r"(r3) : "r"(addr))

#define LDM_X2(r0,r1, addr) \
    asm volatile("ldmatrix.sync.aligned.m8n8.x2.shared.b16 {%0,%1}, [%2];" \
                 : "=r"(r0),"=r"(r1) : "r"(addr))

#define MMA16816(c0,c1,c2,c3, a0,a1,a2,a3, b0,b1) \
    asm volatile("mma.sync.aligned.m16n8k16.row.col.f32.bf16.bf16.f32 " \
                 "{%0,%1,%2,%3}, {%4,%5,%6,%7}, {%8,%9}, {%0,%1,%2,%3};" \
                 : "+f"(c0),"+f"(c1),"+f"(c2),"+f"(c3) \
                 : "r"(a0),"r"(a1),"r"(a2),"r"(a3),"r"(b0),"r"(b1))

#define STAGE_LOAD(st, kb) do {                                                   \
    _Pragma("unroll")                                                             \
    for (int i_ = 0; i_ < 2; i_++) {                                              \
        int c_ = tid + (i_ << 8);                                                 \
        int r_ = c_ >> 2, k8_ = c_ & 3;                                           \
        uint32_t off_ = (uint32_t)((st) * STAGE_BYTES + r_ * (LDT*2) + k8_ * 16); \
        size_t ga_ = (size_t)(mBase + r_) * D_ + (kb) + k8_ * 8;                  \
        size_t gb_ = (size_t)(nBase + r_) * D_ + (kb) + k8_ * 8;                  \
        CP16(smBase + off_,                Ahi + ga_);                            \
        CP16(smBase + TILE_BYTES + off_,   Alo + ga_);                            \
        CP16(smBase + 2*TILE_BYTES + off_, Bhi + gb_);                            \
        CP16(smBase + 3*TILE_BYTES + off_, Blo + gb_);                            \
    }                                                                             \
    asm volatile("cp.async.commit_group;\n" ::: "memory");                        \
} while (0)

extern "C" __global__ __launch_bounds__(256) void gemm_bf16x3(
    const __nv_bfloat16* __restrict__ Ahi, const __nv_bfloat16* __restrict__ Alo,
    const __nv_bfloat16* __restrict__ Bhi, const __nv_bfloat16* __restrict__ Blo,
    const float* __restrict__ bias, float* __restrict__ outp, int mode)
{
    extern __shared__ __nv_bfloat16 sm[];
    const int tid  = threadIdx.x;
    const int wid  = tid >> 5, lane = tid & 31;
    const int wm   = wid >> 2, wn = wid & 3;          // 2 x 4 warp grid
    const int mBase = blockIdx.y * BM;
    const int nBase = blockIdx.x * BN;
    const uint32_t smBase = (uint32_t)__cvta_generic_to_shared(sm);

    float c[4][4][4];
    #pragma unroll
    for (int mi = 0; mi < 4; mi++)
        #pragma unroll
        for (int ni = 0; ni < 4; ni++)
            #pragma unroll
            for (int e = 0; e < 4; e++) c[mi][ni][e] = 0.f;

    // ldmatrix per-lane addressing
    const int aRow = (lane & 7) + ((lane >> 3) & 1) * 8;  // row within 16-row frag
    const int aK   = (lane >> 4) * 8;                     // k offset (0 or 8)
    const int bRow = lane & 7;
    const int bK   = ((lane >> 3) & 1) * 8;

    STAGE_LOAD(0, 0);

    for (int kt = 0; kt < D_ / BK; kt++) {
        if (kt + 1 < D_ / BK) {
            STAGE_LOAD((kt + 1) & 1, (kt + 1) * BK);
            asm volatile("cp.async.wait_group 1;\n" ::: "memory");
        } else {
            asm volatile("cp.async.wait_group 0;\n" ::: "memory");
        }
        __syncthreads();

        const uint32_t stBase = smBase + (uint32_t)((kt & 1) * STAGE_BYTES);
        #pragma unroll
        for (int kk = 0; kk < 2; kk++) {
            const int k0 = kk * 16;
            uint32_t ah[4][4], al[4][4], bh[4][2], bl[4][2];
            #pragma unroll
            for (int mi = 0; mi < 4; mi++) {
                int row = wm * 64 + mi * 16 + aRow;
                uint32_t off = stBase + (uint32_t)(row * LDT + k0 + aK) * 2;
                LDM_X4(ah[mi][0], ah[mi][1], ah[mi][2], ah[mi][3], off);
                LDM_X4(al[mi][0], al[mi][1], al[mi][2], al[mi][3], off + TILE_BYTES);
            }
            #pragma unroll
            for (int ni = 0; ni < 4; ni++) {
                int row = wn * 32 + ni * 8 + bRow;
                uint32_t off = stBase + 2 * TILE_BYTES +
                               (uint32_t)(row * LDT + k0 + bK) * 2;
                LDM_X2(bh[ni][0], bh[ni][1], off);
                LDM_X2(bl[ni][0], bl[ni][1], off + TILE_BYTES);
            }
            #pragma unroll
            for (int mi = 0; mi < 4; mi++)
                #pragma unroll
                for (int ni = 0; ni < 4; ni++) {
                    MMA16816(c[mi][ni][0], c[mi][ni][1], c[mi][ni][2], c[mi][ni][3],
                             ah[mi][0], ah[mi][1], ah[mi][2], ah[mi][3],
                             bh[ni][0], bh[ni][1]);
                    MMA16816(c[mi][ni][0], c[mi][ni][1], c[mi][ni][2], c[mi][ni][3],
                             ah[mi][0], ah[mi][1], ah[mi][2], ah[mi][3],
                             bl[ni][0], bl[ni][1]);
                    MMA16816(c[mi][ni][0], c[mi][ni][1], c[mi][ni][2], c[mi][ni][3],
                             al[mi][0], al[mi][1], al[mi][2], al[mi][3],
                             bh[ni][0], bh[ni][1]);
                }
        }
        __syncthreads();
    }

    // ---------------- epilogue ----------------
    const int g  = lane >> 2;
    const int th = lane & 3;
    float* qkv = (mode == 0) ? g_Q : (mode == 1) ? g_K : g_V;

    #pragma unroll
    for (int mi = 0; mi < 4; mi++) {
        #pragma unroll
        for (int ni = 0; ni < 4; ni++) {
            int row0 = mBase + wm * 64 + mi * 16 + g;
            int col0 = nBase + wn * 32 + ni * 8 + th * 2;
            #pragma unroll
            for (int e = 0; e < 4; e++) {
                int m = row0 + (e >> 1) * 8;
                int n = col0 + (e & 1);
                float val = c[mi][ni][e] + bias[n];
                if (mode == 3) {
                    outp[(size_t)m * D_ + n] = val;
                } else {
                    int b = m >> 11, s = m & 2047;
                    int h = n >> 6,  dh = n & 63;
                    qkv[(((size_t)(b * H_ + h)) * S_ + s) * DH_ + dh] = val;
                }
            }
        }
    }
}

// ---------------------------------------------------------------------------
// Flash attention (causal), fp32 — unchanged from R1
// ---------------------------------------------------------------------------
#define BQ 128
#define KT 64

__global__ __launch_bounds__(128) void flash_attn() {
    __shared__ float Ks[KT * DH_];
    __shared__ float Vs[KT * DH_];

    const int bh = blockIdx.y;
    const int q0 = blockIdx.x * BQ;
    const int t  = threadIdx.x;
    const int qi = q0 + t;

    const float* Qb = g_Q + (size_t)bh * S_ * DH_;
    const float* Kb = g_K + (size_t)bh * S_ * DH_;
    const float* Vb = g_V + (size_t)bh * S_ * DH_;

    float q[DH_];
    #pragma unroll
    for (int i = 0; i < DH_ / 4; i++) {
        float4 v = *(const float4*)&Qb[(size_t)qi * DH_ + i * 4];
        q[i*4+0] = v.x; q[i*4+1] = v.y; q[i*4+2] = v.z; q[i*4+3] = v.w;
    }

    float o[DH_];
    #pragma unroll
    for (int d = 0; d < DH_; d++) o[d] = 0.f;
    float m = -1e30f, l = 0.f;
    const float scale = 0.125f;

    const int kend = q0 + BQ;
    for (int kt = 0; kt < kend; kt += KT) {
        __syncthreads();
        const float4* Kg = (const float4*)&Kb[(size_t)kt * DH_];
        const float4* Vg = (const float4*)&Vb[(size_t)kt * DH_];
        float4* Ks4 = (float4*)Ks;
        float4* Vs4 = (float4*)Vs;
        #pragma unroll
        for (int r = 0; r < 8; r++) {
            Ks4[r * 128 + t] = Kg[r * 128 + t];
            Vs4[r * 128 + t] = Vg[r * 128 + t];
        }
        __syncthreads();

        #pragma unroll 1
        for (int j0 = 0; j0 < KT; j0 += 16) {
            float sreg[16];
            float tmax = -1e30f;
            #pragma unroll
            for (int jj = 0; jj < 16; jj++) {
                const int kidx = kt + j0 + jj;
                const float4* k4 = (const float4*)&Ks[(j0 + jj) * DH_];
                float s0 = 0.f, s1 = 0.f, s2 = 0.f, s3 = 0.f;
                #pragma unroll
                for (int d4 = 0; d4 < DH_ / 4; d4++) {
                    float4 kv = k4[d4];
                    s0 += q[d4*4+0] * kv.x;
                    s1 += q[d4*4+1] * kv.y;
                    s2 += q[d4*4+2] * kv.z;
                    s3 += q[d4*4+3] * kv.w;
                }
                float s = ((s0 + s1) + (s2 + s3)) * scale;
                s = (kidx <= qi) ? s : -1e30f;
                sreg[jj] = s;
                tmax = fmaxf(tmax, s);
            }
            float mnew = fmaxf(m, tmax);
            if (mnew > m) {
                float corr = __expf(m - mnew);
                l *= corr;
                #pragma unroll
                for (int d = 0; d < DH_; d++) o[d] *= corr;
                m = mnew;
            }
            #pragma unroll
            for (int jj = 0; jj < 16; jj++) {
                float p = __expf(sreg[jj] - m);
                l += p;
                const float4* v4 = (const float4*)&Vs[(j0 + jj) * DH_];
                #pragma unroll
                for (int d4 = 0; d4 < DH_ / 4; d4++) {
                    float4 vv = v4[d4];
                    o[d4*4+0] += p * vv.x;
                    o[d4*4+1] += p * vv.y;
                    o[d4*4+2] += p * vv.z;
                    o[d4*4+3] += p * vv.w;
                }
            }
        }
    }

    const float inv = 1.0f / l;
    const int b = bh >> 4;
    const int h = bh & 15;
    float* dst = &g_AO[((size_t)(b * S_ + qi)) * D_ + h * DH_];
    #pragma unroll
    for (int d4 = 0; d4 < DH_ / 4; d4++) {
        float4 vv;
        vv.x = o[d4*4+0] * inv;
        vv.y = o[d4*4+1] * inv;
        vv.z = o[d4*4+2] * inv;
        vv.w = o[d4*4+3] * inv;
        *(float4*)&dst[d4 * 4] = vv;
    }
}

// ---------------------------------------------------------------------------
extern "C" void kernel_launch(void* const* d_in, const int* in_sizes, int n_in,
                              void* d_out, int out_size) {
    const float* x  = (const float*)d_in[0];
    const float* Wq = (const float*)d_in[1];
    const float* bq = (const float*)d_in[2];
    const float* Wk = (const float*)d_in[3];
    const float* bk = (const float*)d_in[4];
    const float* Wv = (const float*)d_in[5];
    const float* bv = (const float*)d_in[6];
    const float* Wo = (const float*)d_in[7];
    const float* bo = (const float*)d_in[8];
    float* out = (float*)d_out;

    static int smem_set = 0;
    cudaFuncSetAttribute(gemm_bf16x3, cudaFuncAttributeMaxDynamicSharedMemorySize,
                         2 * STAGE_BYTES);
    (void)smem_set;

    // resolve device scratch addresses
    __nv_bfloat16 *xhi, *xlo, *aohi, *aolo, *whi, *wlo;
    cudaGetSymbolAddress((void**)&xhi,  g_xhi);
    cudaGetSymbolAddress((void**)&xlo,  g_xlo);
    cudaGetSymbolAddress((void**)&aohi, g_AOhi);
    cudaGetSymbolAddress((void**)&aolo, g_AOlo);
    cudaGetSymbolAddress((void**)&whi,  g_Whi);
    cudaGetSymbolAddress((void**)&wlo,  g_Wlo);
    float* ao;
    cudaGetSymbolAddress((void**)&ao, g_AO);

    const int nx4 = (M_ * D_) / 4;     // 2M
    const int nw4 = (D_ * D_) / 4;     // 256K

    // split conversions
    cvt_split<<<(nx4 + 255) / 256, 256>>>((const float4*)x,
        (__nv_bfloat162*)xhi, (__nv_bfloat162*)xlo, nx4);
    const float* Ws[4] = {Wq, Wk, Wv, Wo};
    for (int i = 0; i < 4; i++)
        cvt_split<<<(nw4 + 255) / 256, 256>>>((const float4*)Ws[i],
            (__nv_bfloat162*)(whi + (size_t)i * D_ * D_),
            (__nv_bfloat162*)(wlo + (size_t)i * D_ * D_), nw4);

    dim3 gg(D_ / BN, M_ / BM);  // (8, 64)
    gemm_bf16x3<<<gg, 256, 2 * STAGE_BYTES>>>(xhi, xlo,
        whi + 0 * (size_t)D_ * D_, wlo + 0 * (size_t)D_ * D_, bq, nullptr, 0);
    gemm_bf16x3<<<gg, 256, 2 * STAGE_BYTES>>>(xhi, xlo,
        whi + 1 * (size_t)D_ * D_, wlo + 1 * (size_t)D_ * D_, bk, nullptr, 1);
    gemm_bf16x3<<<gg, 256, 2 * STAGE_BYTES>>>(xhi, xlo,
        whi + 2 * (size_t)D_ * D_, wlo + 2 * (size_t)D_ * D_, bv, nullptr, 2);

    dim3 fg(S_ / BQ, B_ * H_);  // (16, 64)
    flash_attn<<<fg, 128>>>();

    cvt_split<<<(nx4 + 255) / 256, 256>>>((const float4*)ao,
        (__nv_bfloat162*)aohi, (__nv_bfloat162*)aolo, nx4);
    gemm_bf16x3<<<gg, 256, 2 * STAGE_BYTES>>>(aohi, aolo,
        whi + 3 * (size_t)D_ * D_, wlo + 3 * (size_t)D_ * D_, bo, out, 3);
}

// round 4
// speedup vs baseline: 3.2634x; 2.0400x over previous
#include <cuda_runtime.h>
#include <cuda_bf16.h>
#include <cstdint>

#define B_  4
#define S_  2048
#define D_  1024
#define H_  16
#define DH_ 64
#define M_  (B_*S_)   // 8192

// ---------------- scratch (static __device__, no allocation) ----------------
__device__ __nv_bfloat16 g_Qhi[(size_t)M_*D_];   // [B,H,S,DH]
__device__ __nv_bfloat16 g_Qlo[(size_t)M_*D_];
__device__ __nv_bfloat16 g_Khi[(size_t)M_*D_];
__device__ __nv_bfloat16 g_Klo[(size_t)M_*D_];
__device__ __nv_bfloat16 g_Vhi[(size_t)M_*D_];
__device__ __nv_bfloat16 g_Vlo[(size_t)M_*D_];
__device__ __nv_bfloat16 g_AOhi[(size_t)M_*D_]; // [B*S, D] merged heads
__device__ __nv_bfloat16 g_AOlo[(size_t)M_*D_];
__device__ __nv_bfloat16 g_xhi[(size_t)M_*D_];
__device__ __nv_bfloat16 g_xlo[(size_t)M_*D_];
__device__ __nv_bfloat16 g_Whi[4][(size_t)D_*D_];
__device__ __nv_bfloat16 g_Wlo[4][(size_t)D_*D_];

// ---------------------------------------------------------------------------
__device__ __forceinline__ void split2(float x, float y, uint32_t& hi, uint32_t& lo) {
    __nv_bfloat16 hx = __float2bfloat16_rn(x);
    __nv_bfloat16 hy = __float2bfloat16_rn(y);
    __nv_bfloat16 lx = __float2bfloat16_rn(x - __bfloat162float(hx));
    __nv_bfloat16 ly = __float2bfloat16_rn(y - __bfloat162float(hy));
    __nv_bfloat162 Hv(hx, hy), Lv(lx, ly);
    hi = *(uint32_t*)&Hv;
    lo = *(uint32_t*)&Lv;
}

// ---------------------------------------------------------------------------
// split-precision conversion: fp32 -> (bf16 hi, bf16 lo)
// ---------------------------------------------------------------------------
__global__ __launch_bounds__(256) void cvt_split(const float4* __restrict__ src,
                                                 __nv_bfloat162* __restrict__ hi,
                                                 __nv_bfloat162* __restrict__ lo,
                                                 int n4) {
    int i = blockIdx.x * blockDim.x + threadIdx.x;
    if (i >= n4) return;
    float4 v = src[i];
    __nv_bfloat16 hx = __float2bfloat16_rn(v.x);
    __nv_bfloat16 hy = __float2bfloat16_rn(v.y);
    __nv_bfloat16 hz = __float2bfloat16_rn(v.z);
    __nv_bfloat16 hw = __float2bfloat16_rn(v.w);
    __nv_bfloat16 lx = __float2bfloat16_rn(v.x - __bfloat162float(hx));
    __nv_bfloat16 ly = __float2bfloat16_rn(v.y - __bfloat162float(hy));
    __nv_bfloat16 lz = __float2bfloat16_rn(v.z - __bfloat162float(hz));
    __nv_bfloat16 lw = __float2bfloat16_rn(v.w - __bfloat162float(hw));
    hi[2*i]   = __nv_bfloat162(hx, hy);
    hi[2*i+1] = __nv_bfloat162(hz, hw);
    lo[2*i]   = __nv_bfloat162(lx, ly);
    lo[2*i+1] = __nv_bfloat162(lz, lw);
}

// ---------------------------------------------------------------------------
// common PTX macros
// ---------------------------------------------------------------------------
#define CP16(dst, src) \
    asm volatile("cp.async.cg.shared.global [%0], [%1], 16;\n" :: "r"(dst), "l"(src))
#define CP_COMMIT() asm volatile("cp.async.commit_group;\n" ::: "memory")
#define CP_WAIT(n)  asm volatile("cp.async.wait_group %0;\n" :: "n"(n) : "memory")

#define LDM_X4(r0,r1,r2,r3, addr) \
    asm volatile("ldmatrix.sync.aligned.m8n8.x4.shared.b16 {%0,%1,%2,%3}, [%4];" \
                 : "=r"(r0),"=r"(r1),"=r"(r2),"=r"(r3) : "r"(addr))
#define LDM_X2(r0,r1, addr) \
    asm volatile("ldmatrix.sync.aligned.m8n8.x2.shared.b16 {%0,%1}, [%2];" \
                 : "=r"(r0),"=r"(r1) : "r"(addr))
#define LDM_X2T(r0,r1, addr) \
    asm volatile("ldmatrix.sync.aligned.m8n8.x2.trans.shared.b16 {%0,%1}, [%2];" \
                 : "=r"(r0),"=r"(r1) : "r"(addr))

#define MMA16816(c0,c1,c2,c3, a0,a1,a2,a3, b0,b1) \
    asm volatile("mma.sync.aligned.m16n8k16.row.col.f32.bf16.bf16.f32 " \
                 "{%0,%1,%2,%3}, {%4,%5,%6,%7}, {%8,%9}, {%0,%1,%2,%3};" \
                 : "+f"(c0),"+f"(c1),"+f"(c2),"+f"(c3) \
                 : "r"(a0),"r"(a1),"r"(a2),"r"(a3),"r"(b0),"r"(b1))

// ---------------------------------------------------------------------------
// bf16x3 split GEMM:  C[m,n] = sum_k A[m,k]*W[n,k] + bias[n]
// 128x128x32 tiles, 256 threads (8 warps = 2m x 4n), warp tile 64x32.
// mode 0/1/2: split-store into g_{Q,K,V}{hi,lo} as [B,H,S,DH]
// mode 3:     fp32 store to outp
// ---------------------------------------------------------------------------
#define BM 128
#define BN 128
#define BK 32
#define LDT 40                 // bf16 per smem row (80 bytes, 5 chunks of 16B)
#define TILE_BYTES (BM*LDT*2)  // 10240
#define STAGE_BYTES (4*TILE_BYTES) // 40960

#define STAGE_LOAD(st, kb) do {                                                   \
    _Pragma("unroll")                                                             \
    for (int i_ = 0; i_ < 2; i_++) {                                              \
        int c_ = tid + (i_ << 8);                                                 \
        int r_ = c_ >> 2, k8_ = c_ & 3;                                           \
        uint32_t off_ = (uint32_t)((st) * STAGE_BYTES + r_ * (LDT*2) + k8_ * 16); \
        size_t ga_ = (size_t)(mBase + r_) * D_ + (kb) + k8_ * 8;                  \
        size_t gb_ = (size_t)(nBase + r_) * D_ + (kb) + k8_ * 8;                  \
        CP16(smBase + off_,                Ahi + ga_);                            \
        CP16(smBase + TILE_BYTES + off_,   Alo + ga_);                            \
        CP16(smBase + 2*TILE_BYTES + off_, Bhi + gb_);                            \
        CP16(smBase + 3*TILE_BYTES + off_, Blo + gb_);                            \
    }                                                                             \
    CP_COMMIT();                                                                  \
} while (0)

extern "C" __global__ __launch_bounds__(256) void gemm_bf16x3(
    const __nv_bfloat16* __restrict__ Ahi, const __nv_bfloat16* __restrict__ Alo,
    const __nv_bfloat16* __restrict__ Bhi, const __nv_bfloat16* __restrict__ Blo,
    const float* __restrict__ bias, float* __restrict__ outp, int mode)
{
    extern __shared__ __nv_bfloat16 sm[];
    const int tid  = threadIdx.x;
    const int wid  = tid >> 5, lane = tid & 31;
    const int wm   = wid >> 2, wn = wid & 3;
    const int mBase = blockIdx.y * BM;
    const int nBase = blockIdx.x * BN;
    const uint32_t smBase = (uint32_t)__cvta_generic_to_shared(sm);

    float c[4][4][4];
    #pragma unroll
    for (int mi = 0; mi < 4; mi++)
        #pragma unroll
        for (int ni = 0; ni < 4; ni++)
            #pragma unroll
            for (int e = 0; e < 4; e++) c[mi][ni][e] = 0.f;

    const int aRow = (lane & 7) + ((lane >> 3) & 1) * 8;
    const int aK   = (lane >> 4) * 8;
    const int bRow = lane & 7;
    const int bK   = ((lane >> 3) & 1) * 8;

    STAGE_LOAD(0, 0);

    for (int kt = 0; kt < D_ / BK; kt++) {
        if (kt + 1 < D_ / BK) {
            STAGE_LOAD((kt + 1) & 1, (kt + 1) * BK);
            CP_WAIT(1);
        } else {
            CP_WAIT(0);
        }
        __syncthreads();

        const uint32_t stBase = smBase + (uint32_t)((kt & 1) * STAGE_BYTES);
        #pragma unroll
        for (int kk = 0; kk < 2; kk++) {
            const int k0 = kk * 16;
            uint32_t ah[4][4], al[4][4], bh[4][2], bl[4][2];
            #pragma unroll
            for (int mi = 0; mi < 4; mi++) {
                int row = wm * 64 + mi * 16 + aRow;
                uint32_t off = stBase + (uint32_t)(row * LDT + k0 + aK) * 2;
                LDM_X4(ah[mi][0], ah[mi][1], ah[mi][2], ah[mi][3], off);
                LDM_X4(al[mi][0], al[mi][1], al[mi][2], al[mi][3], off + TILE_BYTES);
            }
            #pragma unroll
            for (int ni = 0; ni < 4; ni++) {
                int row = wn * 32 + ni * 8 + bRow;
                uint32_t off = stBase + 2 * TILE_BYTES +
                               (uint32_t)(row * LDT + k0 + bK) * 2;
                LDM_X2(bh[ni][0], bh[ni][1], off);
                LDM_X2(bl[ni][0], bl[ni][1], off + TILE_BYTES);
            }
            #pragma unroll
            for (int mi = 0; mi < 4; mi++)
                #pragma unroll
                for (int ni = 0; ni < 4; ni++) {
                    MMA16816(c[mi][ni][0], c[mi][ni][1], c[mi][ni][2], c[mi][ni][3],
                             ah[mi][0], ah[mi][1], ah[mi][2], ah[mi][3],
                             bh[ni][0], bh[ni][1]);
                    MMA16816(c[mi][ni][0], c[mi][ni][1], c[mi][ni][2], c[mi][ni][3],
                             ah[mi][0], ah[mi][1], ah[mi][2], ah[mi][3],
                             bl[ni][0], bl[ni][1]);
                    MMA16816(c[mi][ni][0], c[mi][ni][1], c[mi][ni][2], c[mi][ni][3],
                             al[mi][0], al[mi][1], al[mi][2], al[mi][3],
                             bh[ni][0], bh[ni][1]);
                }
        }
        __syncthreads();
    }

    // ---------------- epilogue ----------------
    const int g  = lane >> 2;
    const int th = lane & 3;

    if (mode == 3) {
        #pragma unroll
        for (int mi = 0; mi < 4; mi++)
            #pragma unroll
            for (int ni = 0; ni < 4; ni++) {
                int row0 = mBase + wm * 64 + mi * 16 + g;
                int col0 = nBase + wn * 32 + ni * 8 + th * 2;
                #pragma unroll
                for (int e = 0; e < 4; e++) {
                    int m = row0 + (e >> 1) * 8;
                    int n = col0 + (e & 1);
                    outp[(size_t)m * D_ + n] = c[mi][ni][e] + bias[n];
                }
            }
    } else {
        __nv_bfloat16* dhi = (mode == 0) ? g_Qhi : (mode == 1) ? g_Khi : g_Vhi;
        __nv_bfloat16* dlo = (mode == 0) ? g_Qlo : (mode == 1) ? g_Klo : g_Vlo;
        #pragma unroll
        for (int mi = 0; mi < 4; mi++)
            #pragma unroll
            for (int ni = 0; ni < 4; ni++) {
                int row0 = mBase + wm * 64 + mi * 16 + g;
                int col0 = nBase + wn * 32 + ni * 8 + th * 2;
                float b0v = bias[col0], b1v = bias[col0 + 1];
                int hh = col0 >> 6, dh = col0 & 63;
                #pragma unroll
                for (int pr = 0; pr < 2; pr++) {
                    int m = row0 + pr * 8;
                    int b = m >> 11, s = m & 2047;
                    float v0 = c[mi][ni][pr*2]   + b0v;
                    float v1 = c[mi][ni][pr*2+1] + b1v;
                    uint32_t hv, lv;
                    split2(v0, v1, hv, lv);
                    size_t idx = (((size_t)(b * H_ + hh)) * S_ + s) * DH_ + dh;
                    *(uint32_t*)&dhi[idx] = hv;
                    *(uint32_t*)&dlo[idx] = lv;
                }
            }
    }
}

// ---------------------------------------------------------------------------
// Tensor-core flash attention (causal), bf16x3 split for QK^T and PV.
// CTA: 64 q rows, 4 warps (16 rows each). Key tiles of 64.
// Row pitch LDF = 72 bf16 = 144B = 9 x 16B chunks (odd -> conflict-free,
// and 144B actually fits a full 128B row unlike the R3 bug).
// ---------------------------------------------------------------------------
#define LDF 72
#define FTILEB (64*LDF*2)   // 9216 bytes per 64x64 bf16 tile

__global__ __launch_bounds__(128) void flash_tc() {
    __shared__ __nv_bfloat16 sK[2 * 64 * LDF];   // hi, lo   (18432 B)
    __shared__ __nv_bfloat16 sV[2 * 64 * LDF];   // hi, lo   (18432 B)

    const int bh = blockIdx.y;
    const int Qb = blockIdx.x;
    const int q0 = Qb * 64;
    const int tid  = threadIdx.x;
    const int wq   = tid >> 5, lane = tid & 31;
    const int g    = lane >> 2, th = lane & 3;

    const size_t base = (size_t)bh * S_ * DH_;
    const __nv_bfloat16* Qh = g_Qhi + base;
    const __nv_bfloat16* Ql = g_Qlo + base;
    const __nv_bfloat16* Kh = g_Khi + base;
    const __nv_bfloat16* Kl = g_Klo + base;
    const __nv_bfloat16* Vh = g_Vhi + base;
    const __nv_bfloat16* Vl = g_Vlo + base;

    const uint32_t smK = (uint32_t)__cvta_generic_to_shared(sK);
    const uint32_t smV = (uint32_t)__cvta_generic_to_shared(sV);

    // ---- stage Q tile (hi, lo) into sK, pull fragments to registers ----
    // 2 tiles x 64 rows x 8 chunks(16B) = 1024 chunks, 128 threads x 8
    #pragma unroll
    for (int i = 0; i < 8; i++) {
        int c = tid + i * 128;
        int t = c >> 9, r = (c >> 3) & 63, c8 = c & 7;
        const __nv_bfloat16* src = (t ? Ql : Qh) + (size_t)(q0 + r) * DH_ + c8 * 8;
        CP16(smK + (uint32_t)(t * FTILEB + r * (LDF*2) + c8 * 16), src);
    }
    CP_COMMIT();
    CP_WAIT(0);
    __syncthreads();

    uint32_t qh[4][4], ql[4][4];
    {
        const int aRow = lane & 15, aK = (lane >> 4) * 8;
        int row = wq * 16 + aRow;
        #pragma unroll
        for (int j = 0; j < 4; j++) {
            uint32_t off = smK + (uint32_t)(row * LDF + j * 16 + aK) * 2;
            LDM_X4(qh[j][0], qh[j][1], qh[j][2], qh[j][3], off);
            LDM_X4(ql[j][0], ql[j][1], ql[j][2], ql[j][3], off + FTILEB);
        }
    }

    float m0 = -1e30f, m1 = -1e30f, l0 = 0.f, l1 = 0.f;
    float co[8][4];
    #pragma unroll
    for (int nt = 0; nt < 8; nt++)
        #pragma unroll
        for (int e = 0; e < 4; e++) co[nt][e] = 0.f;

    const int bRow  = lane & 7;
    const int bK    = ((lane >> 3) & 1) * 8;
    const int vRow0 = (lane & 7) + ((lane >> 3) & 1) * 8;

    for (int kt = 0; kt <= Qb; kt++) {
        __syncthreads();   // smem reuse guard
        // 4 tiles x 512 chunks = 2048, 128 threads x 16
        #pragma unroll
        for (int i = 0; i < 16; i++) {
            int c = tid + i * 128;
            int t = c >> 9;                 // 0..3
            int r = (c >> 3) & 63, c8 = c & 7;
            const __nv_bfloat16* srcb = (t == 0) ? Kh : (t == 1) ? Kl
                                       : (t == 2) ? Vh : Vl;
            uint32_t dst = ((t < 2) ? smK + t * FTILEB : smV + (t - 2) * FTILEB)
                           + (uint32_t)(r * (LDF*2) + c8 * 16);
            CP16(dst, srcb + (size_t)(kt * 64 + r) * DH_ + c8 * 8);
        }
        CP_COMMIT();
        CP_WAIT(0);
        __syncthreads();

        // ---- S = Q K^T (bf16x3) ----
        float cs[8][4];
        #pragma unroll
        for (int nt = 0; nt < 8; nt++)
            #pragma unroll
            for (int e = 0; e < 4; e++) cs[nt][e] = 0.f;

        #pragma unroll
        for (int nt = 0; nt < 8; nt++) {
            #pragma unroll
            for (int j = 0; j < 4; j++) {
                uint32_t off = smK + (uint32_t)((nt*8 + bRow) * LDF + j*16 + bK) * 2;
                uint32_t k0, k1, k2, k3;
                LDM_X2(k0, k1, off);
                LDM_X2(k2, k3, off + FTILEB);
                MMA16816(cs[nt][0], cs[nt][1], cs[nt][2], cs[nt][3],
                         qh[j][0], qh[j][1], qh[j][2], qh[j][3], k0, k1);
                MMA16816(cs[nt][0], cs[nt][1], cs[nt][2], cs[nt][3],
                         qh[j][0], qh[j][1], qh[j][2], qh[j][3], k2, k3);
                MMA16816(cs[nt][0], cs[nt][1], cs[nt][2], cs[nt][3],
                         ql[j][0], ql[j][1], ql[j][2], ql[j][3], k0, k1);
            }
        }

        // ---- scale + causal mask ----
        const float scale = 0.125f;
        if (kt == Qb) {
            #pragma unroll
            for (int nt = 0; nt < 8; nt++) {
                int kn = kt * 64 + nt * 8 + th * 2;
                #pragma unroll
                for (int e = 0; e < 4; e++) {
                    int kidx = kn + (e & 1);
                    int qi   = q0 + wq * 16 + g + (e >> 1) * 8;
                    cs[nt][e] = (kidx <= qi) ? cs[nt][e] * scale : -1e30f;
                }
            }
        } else {
            #pragma unroll
            for (int nt = 0; nt < 8; nt++)
                #pragma unroll
                for (int e = 0; e < 4; e++) cs[nt][e] *= scale;
        }

        // ---- online softmax ----
        float tm0 = -1e30f, tm1 = -1e30f;
        #pragma unroll
        for (int nt = 0; nt < 8; nt++) {
            tm0 = fmaxf(tm0, fmaxf(cs[nt][0], cs[nt][1]));
            tm1 = fmaxf(tm1, fmaxf(cs[nt][2], cs[nt][3]));
        }
        tm0 = fmaxf(tm0, __shfl_xor_sync(0xffffffffu, tm0, 1));
        tm0 = fmaxf(tm0, __shfl_xor_sync(0xffffffffu, tm0, 2));
        tm1 = fmaxf(tm1, __shfl_xor_sync(0xffffffffu, tm1, 1));
        tm1 = fmaxf(tm1, __shfl_xor_sync(0xffffffffu, tm1, 2));

        float mn0 = fmaxf(m0, tm0), mn1 = fmaxf(m1, tm1);
        float cr0 = __expf(m0 - mn0), cr1 = __expf(m1 - mn1);
        m0 = mn0; m1 = mn1;
        l0 *= cr0; l1 *= cr1;
        #pragma unroll
        for (int nt = 0; nt < 8; nt++) {
            co[nt][0] *= cr0; co[nt][1] *= cr0;
            co[nt][2] *= cr1; co[nt][3] *= cr1;
        }

        // ---- p = exp(s - m), split to bf16 hi/lo A-fragments ----
        uint32_t ah[4][4], al[4][4];
        #pragma unroll
        for (int nt = 0; nt < 8; nt++) {
            float p0 = __expf(cs[nt][0] - m0);
            float p1 = __expf(cs[nt][1] - m0);
            float p2 = __expf(cs[nt][2] - m1);
            float p3 = __expf(cs[nt][3] - m1);
            l0 += p0 + p1;
            l1 += p2 + p3;
            int j = nt >> 1, hh = (nt & 1) * 2;
            split2(p0, p2, ah[j][hh],     al[j][hh]);      // (g,k), (g+8,k)
            split2(p1, p3, ah[j][hh + 1], al[j][hh + 1]);
        }
        // NOTE: a-frag ordering is {a0=(g,klo), a1=(g+8,klo), a2=(g,khi), a3=(g+8,khi)}
        // with each reg packing (k, k+1) as bf16x2. p0,p1 are (g, k),(g, k+1) and
        // p2,p3 are (g+8, k),(g+8, k+1) — so a0 packs (p0,p1) and a1 packs (p2,p3):
        // fix the two split2 calls accordingly (see corrected lines below).

        // corrected packing (overwrites the above):
        #pragma unroll
        for (int nt = 0; nt < 8; nt++) {
            float p0 = __expf(cs[nt][0] - m0);
            float p1 = __expf(cs[nt][1] - m0);
            float p2 = __expf(cs[nt][2] - m1);
            float p3 = __expf(cs[nt][3] - m1);
            int j = nt >> 1, hh = (nt & 1) * 2;
            split2(p0, p1, ah[j][hh],     al[j][hh]);      // row g,   keys k..k+1
            split2(p2, p3, ah[j][hh + 1], al[j][hh + 1]);  // row g+8, keys k..k+1
        }

        // ---- O += P V (bf16x3) ----
        #pragma unroll
        for (int nt = 0; nt < 8; nt++) {
            #pragma unroll
            for (int j = 0; j < 4; j++) {
                uint32_t off = smV + (uint32_t)((j*16 + vRow0) * LDF + nt*8) * 2;
                uint32_t v0, v1, w0, w1;
                LDM_X2T(v0, v1, off);
                LDM_X2T(w0, w1, off + FTILEB);
                MMA16816(co[nt][0], co[nt][1], co[nt][2], co[nt][3],
                         ah[j][0], ah[j][1], ah[j][2], ah[j][3], v0, v1);
                MMA16816(co[nt][0], co[nt][1], co[nt][2], co[nt][3],
                         ah[j][0], ah[j][1], ah[j][2], ah[j][3], w0, w1);
                MMA16816(co[nt][0], co[nt][1], co[nt][2], co[nt][3],
                         al[j][0], al[j][1], al[j][2], al[j][3], v0, v1);
            }
        }
    }

    // ---- finalize: normalize, split-store to AO hi/lo ----
    l0 += __shfl_xor_sync(0xffffffffu, l0, 1);
    l0 += __shfl_xor_sync(0xffffffffu, l0, 2);
    l1 += __shfl_xor_sync(0xffffffffu, l1, 1);
    l1 += __shfl_xor_sync(0xffffffffu, l1, 2);
    float inv0 = 1.f / l0, inv1 = 1.f / l1;

    const int b  = bh >> 4, hh = bh & 15;
    const int r0 = q0 + wq * 16 + g;
    #pragma unroll
    for (int nt = 0; nt < 8; nt++) {
        int dh = nt * 8 + th * 2;
        size_t i0 = ((size_t)(b * S_ + r0))     * D_ + hh * DH_ + dh;
        size_t i1 = ((size_t)(b * S_ + r0 + 8)) * D_ + hh * DH_ + dh;
        uint32_t hv, lv;
        split2(co[nt][0] * inv0, co[nt][1] * inv0, hv, lv);
        *(uint32_t*)&g_AOhi[i0] = hv;
        *(uint32_t*)&g_AOlo[i0] = lv;
        split2(co[nt][2] * inv1, co[nt][3] * inv1, hv, lv);
        *(uint32_t*)&g_AOhi[i1] = hv;
        *(uint32_t*)&g_AOlo[i1] = lv;
    }
}

// ---------------------------------------------------------------------------
extern "C" void kernel_launch(void* const* d_in, const int* in_sizes, int n_in,
                              void* d_out, int out_size) {
    const float* x  = (const float*)d_in[0];
    const float* Wq = (const float*)d_in[1];
    const float* bq = (const float*)d_in[2];
    const float* Wk = (const float*)d_in[3];
    const float* bk = (const float*)d_in[4];
    const float* Wv = (const float*)d_in[5];
    const float* bv = (const float*)d_in[6];
    const float* Wo = (const float*)d_in[7];
    const float* bo = (const float*)d_in[8];
    float* out = (float*)d_out;

    cudaFuncSetAttribute(gemm_bf16x3, cudaFuncAttributeMaxDynamicSharedMemorySize,
                         2 * STAGE_BYTES);

    __nv_bfloat16 *xhi, *xlo, *aohi, *aolo, *whi, *wlo;
    cudaGetSymbolAddress((void**)&xhi,  g_xhi);
    cudaGetSymbolAddress((void**)&xlo,  g_xlo);
    cudaGetSymbolAddress((void**)&aohi, g_AOhi);
    cudaGetSymbolAddress((void**)&aolo, g_AOlo);
    cudaGetSymbolAddress((void**)&whi,  g_Whi);
    cudaGetSymbolAddress((void**)&wlo,  g_Wlo);

    const int nx4 = (M_ * D_) / 4;
    const int nw4 = (D_ * D_) / 4;

    cvt_split<<<(nx4 + 255) / 256, 256>>>((const float4*)x,
        (__nv_bfloat162*)xhi, (__nv_bfloat162*)xlo, nx4);
    const float* Ws[4] = {Wq, Wk, Wv, Wo};
    for (int i = 0; i < 4; i++)
        cvt_split<<<(nw4 + 255) / 256, 256>>>((const float4*)Ws[i],
            (__nv_bfloat162*)(whi + (size_t)i * D_ * D_),
            (__nv_bfloat162*)(wlo + (size_t)i * D_ * D_), nw4);

    dim3 gg(D_ / BN, M_ / BM);  // (8, 64)
    gemm_bf16x3<<<gg, 256, 2 * STAGE_BYTES>>>(xhi, xlo,
        whi + 0 * (size_t)D_ * D_, wlo + 0 * (size_t)D_ * D_, bq, nullptr, 0);
    gemm_bf16x3<<<gg, 256, 2 * STAGE_BYTES>>>(xhi, xlo,
        whi + 1 * (size_t)D_ * D_, wlo + 1 * (size_t)D_ * D_, bk, nullptr, 1);
    gemm_bf16x3<<<gg, 256, 2 * STAGE_BYTES>>>(xhi, xlo,
        whi + 2 * (size_t)D_ * D_, wlo + 2 * (size_t)D_ * D_, bv, nullptr, 2);

    dim3 fg(S_ / 64, B_ * H_);  // (32, 64)
    flash_tc<<<fg, 128>>>();

    gemm_bf16x3<<<gg, 256, 2 * STAGE_BYTES>>>(aohi, aolo,
        whi + 3 * (size_t)D_ * D_, wlo + 3 * (size_t)D_ * D_, bo, out, 3);
}

// round 5
// speedup vs baseline: 3.3573x; 1.0288x over previous
#include <cuda_runtime.h>
#include <cuda_bf16.h>
#include <cstdint>

#define B_  4
#define S_  2048
#define D_  1024
#define H_  16
#define DH_ 64
#define M_  (B_*S_)   // 8192

// ---------------- scratch (static __device__, no allocation) ----------------
__device__ __nv_bfloat16 g_Qhi[(size_t)M_*D_];   // [B,H,S,DH]
__device__ __nv_bfloat16 g_Qlo[(size_t)M_*D_];
__device__ __nv_bfloat16 g_Khi[(size_t)M_*D_];
__device__ __nv_bfloat16 g_Klo[(size_t)M_*D_];
__device__ __nv_bfloat16 g_Vhi[(size_t)M_*D_];
__device__ __nv_bfloat16 g_Vlo[(size_t)M_*D_];
__device__ __nv_bfloat16 g_AOhi[(size_t)M_*D_]; // [B*S, D] merged heads
__device__ __nv_bfloat16 g_AOlo[(size_t)M_*D_];
__device__ __nv_bfloat16 g_xhi[(size_t)M_*D_];
__device__ __nv_bfloat16 g_xlo[(size_t)M_*D_];
__device__ __nv_bfloat16 g_Whi[4][(size_t)D_*D_];
__device__ __nv_bfloat16 g_Wlo[4][(size_t)D_*D_];

// ---------------------------------------------------------------------------
__device__ __forceinline__ void split2(float x, float y, uint32_t& hi, uint32_t& lo) {
    __nv_bfloat16 hx = __float2bfloat16_rn(x);
    __nv_bfloat16 hy = __float2bfloat16_rn(y);
    __nv_bfloat16 lx = __float2bfloat16_rn(x - __bfloat162float(hx));
    __nv_bfloat16 ly = __float2bfloat16_rn(y - __bfloat162float(hy));
    __nv_bfloat162 Hv(hx, hy), Lv(lx, ly);
    hi = *(uint32_t*)&Hv;
    lo = *(uint32_t*)&Lv;
}

// ---------------------------------------------------------------------------
// fused split conversion: x (2M float4) then 4 weights (256K float4 each)
// ---------------------------------------------------------------------------
#define NX4 ((M_*D_)/4)     // 2M
#define NW4 ((D_*D_)/4)     // 256K

__global__ __launch_bounds__(256) void cvt_split_all(const float4* __restrict__ x,
                                                     const float4* __restrict__ w0,
                                                     const float4* __restrict__ w1,
                                                     const float4* __restrict__ w2,
                                                     const float4* __restrict__ w3) {
    int i = blockIdx.x * blockDim.x + threadIdx.x;
    const float4* src;
    __nv_bfloat162 *hi, *lo;
    int idx;
    if (i < NX4) {
        src = x; idx = i;
        hi = (__nv_bfloat162*)g_xhi; lo = (__nv_bfloat162*)g_xlo;
    } else {
        int j = i - NX4;
        int w = j / NW4; idx = j - w * NW4;
        src = (w == 0) ? w0 : (w == 1) ? w1 : (w == 2) ? w2 : w3;
        hi = (__nv_bfloat162*)(g_Whi[0] + (size_t)w * D_ * D_);
        lo = (__nv_bfloat162*)(g_Wlo[0] + (size_t)w * D_ * D_);
    }
    float4 v = src[idx];
    uint32_t h0, l0v, h1, l1v;
    split2(v.x, v.y, h0, l0v);
    split2(v.z, v.w, h1, l1v);
    ((uint32_t*)hi)[2*idx]   = h0;
    ((uint32_t*)hi)[2*idx+1] = h1;
    ((uint32_t*)lo)[2*idx]   = l0v;
    ((uint32_t*)lo)[2*idx+1] = l1v;
}

// ---------------------------------------------------------------------------
// common PTX macros
// ---------------------------------------------------------------------------
#define CP16(dst, src) \
    asm volatile("cp.async.cg.shared.global [%0], [%1], 16;\n" :: "r"(dst), "l"(src))
#define CP_COMMIT() asm volatile("cp.async.commit_group;\n" ::: "memory")
#define CP_WAIT(n)  asm volatile("cp.async.wait_group %0;\n" :: "n"(n) : "memory")

#define LDM_X4(r0,r1,r2,r3, addr) \
    asm volatile("ldmatrix.sync.aligned.m8n8.x4.shared.b16 {%0,%1,%2,%3}, [%4];" \
                 : "=r"(r0),"=r"(r1),"=r"(r2),"=r"(r3) : "r"(addr))
#define LDM_X2(r0,r1, addr) \
    asm volatile("ldmatrix.sync.aligned.m8n8.x2.shared.b16 {%0,%1}, [%2];" \
                 : "=r"(r0),"=r"(r1) : "r"(addr))
#define LDM_X2T(r0,r1, addr) \
    asm volatile("ldmatrix.sync.aligned.m8n8.x2.trans.shared.b16 {%0,%1}, [%2];" \
                 : "=r"(r0),"=r"(r1) : "r"(addr))

#define MMA16816(c0,c1,c2,c3, a0,a1,a2,a3, b0,b1) \
    asm volatile("mma.sync.aligned.m16n8k16.row.col.f32.bf16.bf16.f32 " \
                 "{%0,%1,%2,%3}, {%4,%5,%6,%7}, {%8,%9}, {%0,%1,%2,%3};" \
                 : "+f"(c0),"+f"(c1),"+f"(c2),"+f"(c3) \
                 : "r"(a0),"r"(a1),"r"(a2),"r"(a3),"r"(b0),"r"(b1))

// ---------------------------------------------------------------------------
// bf16x3 split GEMM:  C[m,n] = sum_k A[m,k]*W[n,k] + bias[n]
// 128x128x32 tiles, 256 threads (8 warps = 2m x 4n), warp tile 64x32.
// QKV launch: gridDim.z = 3, mode = z (split-store into g_{Q,K,V}{hi,lo}).
// O launch:   gridDim.z = 1, mode_base = 3 (fp32 store to outp).
// ---------------------------------------------------------------------------
#define BM 128
#define BN 128
#define BK 32
#define LDT 40                 // bf16 per smem row (80 bytes, 5 chunks of 16B)
#define TILE_BYTES (BM*LDT*2)  // 10240
#define STAGE_BYTES (4*TILE_BYTES) // 40960

#define STAGE_LOAD(st, kb) do {                                                   \
    _Pragma("unroll")                                                             \
    for (int i_ = 0; i_ < 2; i_++) {                                              \
        int c_ = tid + (i_ << 8);                                                 \
        int r_ = c_ >> 2, k8_ = c_ & 3;                                           \
        uint32_t off_ = (uint32_t)((st) * STAGE_BYTES + r_ * (LDT*2) + k8_ * 16); \
        size_t ga_ = (size_t)(mBase + r_) * D_ + (kb) + k8_ * 8;                  \
        size_t gb_ = (size_t)(nBase + r_) * D_ + (kb) + k8_ * 8;                  \
        CP16(smBase + off_,                Ahi + ga_);                            \
        CP16(smBase + TILE_BYTES + off_,   Alo + ga_);                            \
        CP16(smBase + 2*TILE_BYTES + off_, Bhi + gb_);                            \
        CP16(smBase + 3*TILE_BYTES + off_, Blo + gb_);                            \
    }                                                                             \
    CP_COMMIT();                                                                  \
} while (0)

extern "C" __global__ __launch_bounds__(256) void gemm_bf16x3(
    const __nv_bfloat16* __restrict__ Ahi, const __nv_bfloat16* __restrict__ Alo,
    const __nv_bfloat16* __restrict__ WhiB, const __nv_bfloat16* __restrict__ WloB,
    const float* __restrict__ b0p, const float* __restrict__ b1p,
    const float* __restrict__ b2p, float* __restrict__ outp, int mode_base)
{
    extern __shared__ __nv_bfloat16 sm[];
    const int zi = blockIdx.z;
    const int mode = mode_base ? 3 : zi;
    const __nv_bfloat16* Bhi = WhiB + (size_t)zi * D_ * D_;
    const __nv_bfloat16* Blo = WloB + (size_t)zi * D_ * D_;
    const float* bias = (zi == 0) ? b0p : (zi == 1) ? b1p : b2p;

    const int tid  = threadIdx.x;
    const int wid  = tid >> 5, lane = tid & 31;
    const int wm   = wid >> 2, wn = wid & 3;
    const int mBase = blockIdx.y * BM;
    const int nBase = blockIdx.x * BN;
    const uint32_t smBase = (uint32_t)__cvta_generic_to_shared(sm);

    float c[4][4][4];
    #pragma unroll
    for (int mi = 0; mi < 4; mi++)
        #pragma unroll
        for (int ni = 0; ni < 4; ni++)
            #pragma unroll
            for (int e = 0; e < 4; e++) c[mi][ni][e] = 0.f;

    const int aRow = (lane & 7) + ((lane >> 3) & 1) * 8;
    const int aK   = (lane >> 4) * 8;
    const int bRow = lane & 7;
    const int bK   = ((lane >> 3) & 1) * 8;

    STAGE_LOAD(0, 0);

    for (int kt = 0; kt < D_ / BK; kt++) {
        if (kt + 1 < D_ / BK) {
            STAGE_LOAD((kt + 1) & 1, (kt + 1) * BK);
            CP_WAIT(1);
        } else {
            CP_WAIT(0);
        }
        __syncthreads();

        const uint32_t stBase = smBase + (uint32_t)((kt & 1) * STAGE_BYTES);
        #pragma unroll
        for (int kk = 0; kk < 2; kk++) {
            const int k0 = kk * 16;
            uint32_t ah[4][4], al[4][4], bh[4][2], bl[4][2];
            #pragma unroll
            for (int mi = 0; mi < 4; mi++) {
                int row = wm * 64 + mi * 16 + aRow;
                uint32_t off = stBase + (uint32_t)(row * LDT + k0 + aK) * 2;
                LDM_X4(ah[mi][0], ah[mi][1], ah[mi][2], ah[mi][3], off);
                LDM_X4(al[mi][0], al[mi][1], al[mi][2], al[mi][3], off + TILE_BYTES);
            }
            #pragma unroll
            for (int ni = 0; ni < 4; ni++) {
                int row = wn * 32 + ni * 8 + bRow;
                uint32_t off = stBase + 2 * TILE_BYTES +
                               (uint32_t)(row * LDT + k0 + bK) * 2;
                LDM_X2(bh[ni][0], bh[ni][1], off);
                LDM_X2(bl[ni][0], bl[ni][1], off + TILE_BYTES);
            }
            #pragma unroll
            for (int mi = 0; mi < 4; mi++)
                #pragma unroll
                for (int ni = 0; ni < 4; ni++) {
                    MMA16816(c[mi][ni][0], c[mi][ni][1], c[mi][ni][2], c[mi][ni][3],
                             ah[mi][0], ah[mi][1], ah[mi][2], ah[mi][3],
                             bh[ni][0], bh[ni][1]);
                    MMA16816(c[mi][ni][0], c[mi][ni][1], c[mi][ni][2], c[mi][ni][3],
                             ah[mi][0], ah[mi][1], ah[mi][2], ah[mi][3],
                             bl[ni][0], bl[ni][1]);
                    MMA16816(c[mi][ni][0], c[mi][ni][1], c[mi][ni][2], c[mi][ni][3],
                             al[mi][0], al[mi][1], al[mi][2], al[mi][3],
                             bh[ni][0], bh[ni][1]);
                }
        }
        __syncthreads();
    }

    // ---------------- epilogue ----------------
    const int g  = lane >> 2;
    const int th = lane & 3;

    if (mode == 3) {
        #pragma unroll
        for (int mi = 0; mi < 4; mi++)
            #pragma unroll
            for (int ni = 0; ni < 4; ni++) {
                int row0 = mBase + wm * 64 + mi * 16 + g;
                int col0 = nBase + wn * 32 + ni * 8 + th * 2;
                #pragma unroll
                for (int e = 0; e < 4; e++) {
                    int m = row0 + (e >> 1) * 8;
                    int n = col0 + (e & 1);
                    outp[(size_t)m * D_ + n] = c[mi][ni][e] + bias[n];
                }
            }
    } else {
        __nv_bfloat16* dhi = (mode == 0) ? g_Qhi : (mode == 1) ? g_Khi : g_Vhi;
        __nv_bfloat16* dlo = (mode == 0) ? g_Qlo : (mode == 1) ? g_Klo : g_Vlo;
        #pragma unroll
        for (int mi = 0; mi < 4; mi++)
            #pragma unroll
            for (int ni = 0; ni < 4; ni++) {
                int row0 = mBase + wm * 64 + mi * 16 + g;
                int col0 = nBase + wn * 32 + ni * 8 + th * 2;
                float b0v = bias[col0], b1v = bias[col0 + 1];
                int hh = col0 >> 6, dh = col0 & 63;
                #pragma unroll
                for (int pr = 0; pr < 2; pr++) {
                    int m = row0 + pr * 8;
                    int b = m >> 11, s = m & 2047;
                    float v0 = c[mi][ni][pr*2]   + b0v;
                    float v1 = c[mi][ni][pr*2+1] + b1v;
                    uint32_t hv, lv;
                    split2(v0, v1, hv, lv);
                    size_t idx = (((size_t)(b * H_ + hh)) * S_ + s) * DH_ + dh;
                    *(uint32_t*)&dhi[idx] = hv;
                    *(uint32_t*)&dlo[idx] = lv;
                }
            }
    }
}

// ---------------------------------------------------------------------------
// Tensor-core flash attention (causal), bf16x3, BQ=128, 8 warps,
// double-buffered K/V tiles (64 keys each), per-warp causal skip.
// ---------------------------------------------------------------------------
#define LDF 72
#define FTILEB (64*LDF*2)      // 9216 B per 64-row tile
#define QTILEB (128*LDF*2)     // 18432 B per 128-row Q tile
#define FSTAGE (4*FTILEB)      // 36864 B: Khi, Klo, Vhi, Vlo
#define FSMEM  (2*FSTAGE)      // 73728 B dynamic

__global__ __launch_bounds__(256) void flash_tc() {
    extern __shared__ __nv_bfloat16 fsm[];
    const uint32_t smBase = (uint32_t)__cvta_generic_to_shared(fsm);

    const int bh = blockIdx.y;
    const int Qb = blockIdx.x;
    const int q0 = Qb * 128;
    const int tid  = threadIdx.x;
    const int wq   = tid >> 5, lane = tid & 31;
    const int g    = lane >> 2, th = lane & 3;

    const size_t base = (size_t)bh * S_ * DH_;
    const __nv_bfloat16* Qh = g_Qhi + base;
    const __nv_bfloat16* Ql = g_Qlo + base;
    const __nv_bfloat16* Kh = g_Khi + base;
    const __nv_bfloat16* Kl = g_Klo + base;
    const __nv_bfloat16* Vh = g_Vhi + base;
    const __nv_bfloat16* Vl = g_Vlo + base;

    // ---- stage Q (128 rows, hi+lo) into stage-0 area, pull frags ----
    // 2 tiles x 128 rows x 8 chunks = 2048 chunks, 256 thr x 8
    #pragma unroll
    for (int i = 0; i < 8; i++) {
        int c = tid + i * 256;
        int t = c >> 10, r = (c >> 3) & 127, c8 = c & 7;
        const __nv_bfloat16* src = (t ? Ql : Qh) + (size_t)(q0 + r) * DH_ + c8 * 8;
        CP16(smBase + (uint32_t)(t * QTILEB + r * (LDF*2) + c8 * 16), src);
    }
    CP_COMMIT();
    CP_WAIT(0);
    __syncthreads();

    uint32_t qh[4][4], ql[4][4];
    {
        const int aRow = lane & 15, aK = (lane >> 4) * 8;
        int row = wq * 16 + aRow;
        #pragma unroll
        for (int j = 0; j < 4; j++) {
            uint32_t off = smBase + (uint32_t)(row * LDF + j * 16 + aK) * 2;
            LDM_X4(qh[j][0], qh[j][1], qh[j][2], qh[j][3], off);
            LDM_X4(ql[j][0], ql[j][1], ql[j][2], ql[j][3], off + QTILEB);
        }
    }
    __syncthreads();   // Q frags read before tile-0 load overwrites stage 0

    float m0 = -1e30f, m1 = -1e30f, l0 = 0.f, l1 = 0.f;
    float co[8][4];
    #pragma unroll
    for (int nt = 0; nt < 8; nt++)
        #pragma unroll
        for (int e = 0; e < 4; e++) co[nt][e] = 0.f;

    const int bRow  = lane & 7;
    const int bK    = ((lane >> 3) & 1) * 8;
    const int vRow0 = (lane & 7) + ((lane >> 3) & 1) * 8;
    const int wmaxq = q0 + wq * 16 + 15;   // max query row this warp owns

    const int NT = 2 * Qb + 2;             // 64-key tiles up to diag

    // tile loader: 4 tiles x 512 chunks = 2048, 256 thr x 8
#define FLOAD(st, ktv) do {                                                       \
    _Pragma("unroll")                                                             \
    for (int i_ = 0; i_ < 8; i_++) {                                              \
        int c_ = tid + i_ * 256;                                                  \
        int t_ = c_ >> 9, r_ = (c_ >> 3) & 63, c8_ = c_ & 7;                      \
        const __nv_bfloat16* s_ = (t_ == 0) ? Kh : (t_ == 1) ? Kl                 \
                                 : (t_ == 2) ? Vh : Vl;                           \
        CP16(smBase + (uint32_t)((st) * FSTAGE + t_ * FTILEB                      \
                                 + r_ * (LDF*2) + c8_ * 16),                      \
             s_ + (size_t)((ktv) * 64 + r_) * DH_ + c8_ * 8);                     \
    }                                                                             \
    CP_COMMIT();                                                                  \
} while (0)

    FLOAD(0, 0);

    for (int kt = 0; kt < NT; kt++) {
        if (kt + 1 < NT) {
            FLOAD((kt + 1) & 1, kt + 1);
            CP_WAIT(1);
        } else {
            CP_WAIT(0);
        }
        __syncthreads();

        if (kt * 64 <= wmaxq) {   // per-warp causal skip
            const uint32_t smK = smBase + (uint32_t)((kt & 1) * FSTAGE);
            const uint32_t smV = smK + 2 * FTILEB;

            // ---- S = Q K^T (bf16x3) ----
            float cs[8][4];
            #pragma unroll
            for (int nt = 0; nt < 8; nt++)
                #pragma unroll
                for (int e = 0; e < 4; e++) cs[nt][e] = 0.f;

            #pragma unroll
            for (int nt = 0; nt < 8; nt++) {
                #pragma unroll
                for (int j = 0; j < 4; j++) {
                    uint32_t off = smK + (uint32_t)((nt*8 + bRow) * LDF + j*16 + bK) * 2;
                    uint32_t k0, k1, k2, k3;
                    LDM_X2(k0, k1, off);
                    LDM_X2(k2, k3, off + FTILEB);
                    MMA16816(cs[nt][0], cs[nt][1], cs[nt][2], cs[nt][3],
                             qh[j][0], qh[j][1], qh[j][2], qh[j][3], k0, k1);
                    MMA16816(cs[nt][0], cs[nt][1], cs[nt][2], cs[nt][3],
                             qh[j][0], qh[j][1], qh[j][2], qh[j][3], k2, k3);
                    MMA16816(cs[nt][0], cs[nt][1], cs[nt][2], cs[nt][3],
                             ql[j][0], ql[j][1], ql[j][2], ql[j][3], k0, k1);
                }
            }

            // ---- scale + causal mask (only diag-overlapping tiles) ----
            const float scale = 0.125f;
            if (kt * 64 + 63 > q0 + wq * 16) {
                #pragma unroll
                for (int nt = 0; nt < 8; nt++) {
                    int kn = kt * 64 + nt * 8 + th * 2;
                    #pragma unroll
                    for (int e = 0; e < 4; e++) {
                        int kidx = kn + (e & 1);
                        int qi   = q0 + wq * 16 + g + (e >> 1) * 8;
                        cs[nt][e] = (kidx <= qi) ? cs[nt][e] * scale : -1e30f;
                    }
                }
            } else {
                #pragma unroll
                for (int nt = 0; nt < 8; nt++)
                    #pragma unroll
                    for (int e = 0; e < 4; e++) cs[nt][e] *= scale;
            }

            // ---- online softmax ----
            float tm0 = -1e30f, tm1 = -1e30f;
            #pragma unroll
            for (int nt = 0; nt < 8; nt++) {
                tm0 = fmaxf(tm0, fmaxf(cs[nt][0], cs[nt][1]));
                tm1 = fmaxf(tm1, fmaxf(cs[nt][2], cs[nt][3]));
            }
            tm0 = fmaxf(tm0, __shfl_xor_sync(0xffffffffu, tm0, 1));
            tm0 = fmaxf(tm0, __shfl_xor_sync(0xffffffffu, tm0, 2));
            tm1 = fmaxf(tm1, __shfl_xor_sync(0xffffffffu, tm1, 1));
            tm1 = fmaxf(tm1, __shfl_xor_sync(0xffffffffu, tm1, 2));

            float mn0 = fmaxf(m0, tm0), mn1 = fmaxf(m1, tm1);
            float cr0 = __expf(m0 - mn0), cr1 = __expf(m1 - mn1);
            m0 = mn0; m1 = mn1;
            l0 *= cr0; l1 *= cr1;
            #pragma unroll
            for (int nt = 0; nt < 8; nt++) {
                co[nt][0] *= cr0; co[nt][1] *= cr0;
                co[nt][2] *= cr1; co[nt][3] *= cr1;
            }

            // ---- p = exp(s - m) -> bf16 hi/lo A-frags ----
            uint32_t ah[4][4], al[4][4];
            #pragma unroll
            for (int nt = 0; nt < 8; nt++) {
                float p0 = __expf(cs[nt][0] - m0);
                float p1 = __expf(cs[nt][1] - m0);
                float p2 = __expf(cs[nt][2] - m1);
                float p3 = __expf(cs[nt][3] - m1);
                l0 += p0 + p1;
                l1 += p2 + p3;
                int j = nt >> 1, hh = (nt & 1) * 2;
                split2(p0, p1, ah[j][hh],     al[j][hh]);      // row g,   keys k..k+1
                split2(p2, p3, ah[j][hh + 1], al[j][hh + 1]);  // row g+8, keys k..k+1
            }

            // ---- O += P V (bf16x3) ----
            #pragma unroll
            for (int nt = 0; nt < 8; nt++) {
                #pragma unroll
                for (int j = 0; j < 4; j++) {
                    uint32_t off = smV + (uint32_t)((j*16 + vRow0) * LDF + nt*8) * 2;
                    uint32_t v0, v1, w0, w1;
                    LDM_X2T(v0, v1, off);
                    LDM_X2T(w0, w1, off + FTILEB);
                    MMA16816(co[nt][0], co[nt][1], co[nt][2], co[nt][3],
                             ah[j][0], ah[j][1], ah[j][2], ah[j][3], v0, v1);
                    MMA16816(co[nt][0], co[nt][1], co[nt][2], co[nt][3],
                             ah[j][0], ah[j][1], ah[j][2], ah[j][3], w0, w1);
                    MMA16816(co[nt][0], co[nt][1], co[nt][2], co[nt][3],
                             al[j][0], al[j][1], al[j][2], al[j][3], v0, v1);
                }
            }
        }
        __syncthreads();   // compute done before next iter overwrites other stage
    }

    // ---- finalize: normalize, split-store to AO hi/lo ----
    l0 += __shfl_xor_sync(0xffffffffu, l0, 1);
    l0 += __shfl_xor_sync(0xffffffffu, l0, 2);
    l1 += __shfl_xor_sync(0xffffffffu, l1, 1);
    l1 += __shfl_xor_sync(0xffffffffu, l1, 2);
    float inv0 = 1.f / l0, inv1 = 1.f / l1;

    const int b  = bh >> 4, hh = bh & 15;
    const int r0 = q0 + wq * 16 + g;
    #pragma unroll
    for (int nt = 0; nt < 8; nt++) {
        int dh = nt * 8 + th * 2;
        size_t i0 = ((size_t)(b * S_ + r0))     * D_ + hh * DH_ + dh;
        size_t i1 = ((size_t)(b * S_ + r0 + 8)) * D_ + hh * DH_ + dh;
        uint32_t hv, lv;
        split2(co[nt][0] * inv0, co[nt][1] * inv0, hv, lv);
        *(uint32_t*)&g_AOhi[i0] = hv;
        *(uint32_t*)&g_AOlo[i0] = lv;
        split2(co[nt][2] * inv1, co[nt][3] * inv1, hv, lv);
        *(uint32_t*)&g_AOhi[i1] = hv;
        *(uint32_t*)&g_AOlo[i1] = lv;
    }
}

// ---------------------------------------------------------------------------
extern "C" void kernel_launch(void* const* d_in, const int* in_sizes, int n_in,
                              void* d_out, int out_size) {
    const float* x  = (const float*)d_in[0];
    const float* Wq = (const float*)d_in[1];
    const float* bq = (const float*)d_in[2];
    const float* Wk = (const float*)d_in[3];
    const float* bk = (const float*)d_in[4];
    const float* Wv = (const float*)d_in[5];
    const float* bv = (const float*)d_in[6];
    const float* Wo = (const float*)d_in[7];
    const float* bo = (const float*)d_in[8];
    float* out = (float*)d_out;

    cudaFuncSetAttribute(gemm_bf16x3, cudaFuncAttributeMaxDynamicSharedMemorySize,
                         2 * STAGE_BYTES);
    cudaFuncSetAttribute(flash_tc, cudaFuncAttributeMaxDynamicSharedMemorySize,
                         FSMEM);

    __nv_bfloat16 *xhi, *xlo, *aohi, *aolo, *whi, *wlo;
    cudaGetSymbolAddress((void**)&xhi,  g_xhi);
    cudaGetSymbolAddress((void**)&xlo,  g_xlo);
    cudaGetSymbolAddress((void**)&aohi, g_AOhi);
    cudaGetSymbolAddress((void**)&aolo, g_AOlo);
    cudaGetSymbolAddress((void**)&whi,  g_Whi);
    cudaGetSymbolAddress((void**)&wlo,  g_Wlo);

    // fused conversions: x + 4 weights
    const int ntot = NX4 + 4 * NW4;
    cvt_split_all<<<(ntot + 255) / 256, 256>>>((const float4*)x,
        (const float4*)Wq, (const float4*)Wk, (const float4*)Wv, (const float4*)Wo);

    // fused QKV projection (gridDim.z = 3)
    dim3 gq(D_ / BN, M_ / BM, 3);
    gemm_bf16x3<<<gq, 256, 2 * STAGE_BYTES>>>(xhi, xlo, whi, wlo,
                                              bq, bk, bv, nullptr, 0);

    dim3 fg(S_ / 128, B_ * H_);  // (16, 64)
    flash_tc<<<fg, 256, FSMEM>>>();

    // O projection
    dim3 go(D_ / BN, M_ / BM, 1);
    gemm_bf16x3<<<go, 256, 2 * STAGE_BYTES>>>(aohi, aolo,
        whi + 3 * (size_t)D_ * D_, wlo + 3 * (size_t)D_ * D_,
        bo, bo, bo, out, 3);
}